// round 14
// baseline (speedup 1.0000x reference)
#include <cuda_runtime.h>
#include <cstdint>
#include <cstddef>

#define NEXP 8
#define HDIM 1024
#define FDIM 4096
#define TTOK 2048

// static device scratch (no allocs allowed)
__device__ float g_xtf [(size_t)NEXP * TTOK * HDIM];   // x pre-converted to tf32
__device__ float g_w1tf[(size_t)NEXP * HDIM * FDIM];   // w1 tf32
__device__ float g_w2tf[(size_t)NEXP * FDIM * HDIM];   // w2 tf32
__device__ float g_inter[(size_t)NEXP * TTOK * FDIM];  // gelu output (tf32-rounded)

#define BM 128
#define BN 128
#define BK 32
#define NSTAGE 3
#define A_WORDS 4096                     // 2 k-half sub-tiles x (128 rows x 16 words)
#define B_WORDS 4352                     // 32 rows x 136 words (padded)
#define STAGE_WORDS (A_WORDS + B_WORDS)  // 8448
#define SMEM_DYN (NSTAGE * STAGE_WORDS * 4)   // 101376 bytes

__device__ __forceinline__ unsigned f2tf(float x) {
    unsigned u;
    asm("cvt.rna.tf32.f32 %0, %1;" : "=r"(u) : "f"(x));
    return u;
}

__device__ __forceinline__ uint32_t smem_u32(const void* p) {
    uint32_t a;
    asm("{ .reg .u64 t; cvta.to.shared.u64 t, %1; cvt.u32.u64 %0, t; }" : "=r"(a) : "l"(p));
    return a;
}

__device__ __forceinline__ void cp16(uint32_t dst, const void* src) {
    asm volatile("cp.async.cg.shared.global [%0], [%1], 16;" :: "r"(dst), "l"(src));
}
__device__ __forceinline__ void cp_commit() {
    asm volatile("cp.async.commit_group;");
}
__device__ __forceinline__ void cp_wait1() {
    asm volatile("cp.async.wait_group %0;" :: "n"(NSTAGE - 2));
}

__device__ __forceinline__ void mma_tf32(float* c,
                                         unsigned a0, unsigned a1, unsigned a2, unsigned a3,
                                         unsigned b0, unsigned b1) {
    asm volatile(
        "mma.sync.aligned.m16n8k8.row.col.f32.tf32.tf32.f32 "
        "{%0,%1,%2,%3}, {%4,%5,%6,%7}, {%8,%9}, {%0,%1,%2,%3};"
        : "+f"(c[0]), "+f"(c[1]), "+f"(c[2]), "+f"(c[3])
        : "r"(a0), "r"(a1), "r"(a2), "r"(a3), "r"(b0), "r"(b1));
}

__device__ __forceinline__ float gelu_tanh(float x) {
    float x3 = x * x * x;
    return 0.5f * x * (1.0f + tanhf(0.7978845608028654f * (x + 0.044715f * x3)));
}

// elementwise fp32 -> tf32(rna)-rounded fp32, float4 grid-stride
__global__ void cvt_tf32_kernel(const float4* __restrict__ in, float4* __restrict__ out, int n4) {
    int i = blockIdx.x * blockDim.x + threadIdx.x;
    const int stride = gridDim.x * blockDim.x;
    for (; i < n4; i += stride) {
        float4 v = in[i];
        float4 o;
        o.x = __uint_as_float(f2tf(v.x));
        o.y = __uint_as_float(f2tf(v.y));
        o.z = __uint_as_float(f2tf(v.z));
        o.w = __uint_as_float(f2tf(v.w));
        out[i] = o;
    }
}

// C[M,N] = A[M,K] @ B[K,N] per expert (blockIdx.z). Inputs are tf32-rounded fp32.
// BM=BN=128, BK=32, 8 warps (2x4), warp tile 64x32, cp.async 3-stage pipeline.
// Low register budget (acc=64) -> 2 CTAs/SM -> 16 warps/SM -> 4 warps/SMSP
// to hide the scalar-LDS fragment-fetch latency under the HMMA stream.
// A smem: per k-half sub-tile of 128x16 words, swizzled:
//   phys(m,k) = kh*2048 + m*16 + (((k>>2) ^ ((m>>1)&3))<<2) + (k&3)
// B smem: row-major [k][n], 32 rows, padded LDB=136.
template <bool GELU>
__global__ __launch_bounds__(256, 2)
void tc_gemm(const float* __restrict__ Aall, const float* __restrict__ Ball,
             float* __restrict__ Call, int M, int N, int K) {
    extern __shared__ unsigned sm[];
    const uint32_t sbase = smem_u32(sm);

    const int tid = threadIdx.x;
    const int lane = tid & 31;
    const int wid = tid >> 5;
    const int warp_m = wid & 1;    // 2 warps along M (64 rows)
    const int warp_n = wid >> 1;   // 4 warps along N (32 cols)
    const int e = blockIdx.z;
    const int mBase = blockIdx.x * BM;
    const int nBase = blockIdx.y * BN;

    const float* A = Aall + (size_t)e * M * K;
    const float* B = Ball + (size_t)e * K * N;
    float* C = Call + (size_t)e * M * N;

    // ---- staging coords (4 x 16B granules each for A and B) ----
    const int ar = tid >> 1;               // A row (0..127)
    const int ah = tid & 1;                // k-half (sub-tile)
    const float* aG = A + (size_t)(mBase + ar) * K + ah * 16;
    const uint32_t aSw = (uint32_t)ah * 2048 + (uint32_t)ar * 16;   // + ((i^s)<<2)
    const uint32_t aS = (ar >> 1) & 3;

    const int bk0 = tid >> 5;              // B k-row base (0..7), rows bk0+8*i
    const int bn4 = (tid & 31) * 4;        // B n offset
    const float* bG = B + (size_t)bk0 * N + nBase + bn4;
    const uint32_t bW0 = (uint32_t)bk0 * 136 + bn4;                 // +1088*i

    const int ntile = K / BK;

    float acc[4][4][4];
#pragma unroll
    for (int i = 0; i < 4; i++)
#pragma unroll
        for (int j = 0; j < 4; j++)
#pragma unroll
            for (int c = 0; c < 4; c++) acc[i][j][c] = 0.0f;

    // issue stage s <- k-tile t (always commits, possibly empty)
    auto issue = [&](int s, int t) {
        if (t < ntile) {
            const uint32_t sa = sbase + (uint32_t)s * (STAGE_WORDS * 4);
            const float* ap = aG + (size_t)t * BK;
#pragma unroll
            for (int i = 0; i < 4; ++i)
                cp16(sa + (aSw + (((uint32_t)i ^ aS) << 2)) * 4, ap + i * 4);
            const uint32_t sb = sa + A_WORDS * 4;
            const float* bp = bG + (size_t)t * BK * N;
#pragma unroll
            for (int i = 0; i < 4; ++i)
                cp16(sb + (bW0 + i * 1088u) * 4, bp + (size_t)i * 8 * N);
        }
        cp_commit();
    };

    // prologue: stages 0..NSTAGE-2
#pragma unroll
    for (int s = 0; s < NSTAGE - 1; ++s) issue(s, s);

    const int q = lane >> 2, r = lane & 3;
    const int sA = (q >> 1) & 3;

    for (int t = 0; t < ntile; ++t) {
        cp_wait1();
        __syncthreads();

        const unsigned* as = sm + (t % NSTAGE) * STAGE_WORDS;
        const unsigned* bs = as + A_WORDS;

#pragma unroll
        for (int ks = 0; ks < 4; ++ks) {
            const unsigned* asub = as + (ks >> 1) * 2048;
            const int ksl = ks & 1;
            const int cLo = ((2 * ksl) ^ sA) << 2;
            const int cHi = ((2 * ksl + 1) ^ sA) << 2;
            unsigned af[4][4];
#pragma unroll
            for (int mt = 0; mt < 4; ++mt) {
                const int base = (warp_m * 64 + mt * 16 + q) * 16 + r;
                af[mt][0] = asub[base + cLo];
                af[mt][1] = asub[base + 128 + cLo];
                af[mt][2] = asub[base + cHi];
                af[mt][3] = asub[base + 128 + cHi];
            }
            unsigned bf[4][2];
#pragma unroll
            for (int nt = 0; nt < 4; ++nt) {
                const int n0 = warp_n * 32 + nt * 8 + q;
                bf[nt][0] = bs[(ks * 8 + r) * 136 + n0];
                bf[nt][1] = bs[(ks * 8 + 4 + r) * 136 + n0];
            }
#pragma unroll
            for (int mt = 0; mt < 4; ++mt)
#pragma unroll
                for (int nt = 0; nt < 4; ++nt)
                    mma_tf32(acc[mt][nt],
                             af[mt][0], af[mt][1], af[mt][2], af[mt][3],
                             bf[nt][0], bf[nt][1]);
        }

        issue((t + NSTAGE - 1) % NSTAGE, t + NSTAGE - 1);
    }

    // ---- epilogue: direct STG (GELU path also rounds to tf32 for GEMM2) ----
#pragma unroll
    for (int mt = 0; mt < 4; ++mt) {
        const int row = mBase + warp_m * 64 + mt * 16 + q;
#pragma unroll
        for (int nt = 0; nt < 4; ++nt) {
            const int col = nBase + warp_n * 32 + nt * 8 + 2 * r;
            float2 v0 = make_float2(acc[mt][nt][0], acc[mt][nt][1]);
            float2 v1 = make_float2(acc[mt][nt][2], acc[mt][nt][3]);
            if (GELU) {
                v0.x = __uint_as_float(f2tf(gelu_tanh(v0.x)));
                v0.y = __uint_as_float(f2tf(gelu_tanh(v0.y)));
                v1.x = __uint_as_float(f2tf(gelu_tanh(v1.x)));
                v1.y = __uint_as_float(f2tf(gelu_tanh(v1.y)));
            }
            *(float2*)(C + (size_t)row * N + col) = v0;
            *(float2*)(C + (size_t)(row + 8) * N + col) = v1;
        }
    }
}

extern "C" void kernel_launch(void* const* d_in, const int* in_sizes, int n_in,
                              void* d_out, int out_size) {
    const float* x  = (const float*)d_in[0];
    const float* w1 = (const float*)d_in[1];
    const float* w2 = (const float*)d_in[2];
    float* out = (float*)d_out;

    float *xtf, *w1tf, *w2tf, *inter;
    cudaGetSymbolAddress((void**)&xtf,  g_xtf);
    cudaGetSymbolAddress((void**)&w1tf, g_w1tf);
    cudaGetSymbolAddress((void**)&w2tf, g_w2tf);
    cudaGetSymbolAddress((void**)&inter, g_inter);

    const int T = (in_sizes[0] / HDIM) / NEXP;   // tokens per expert (2048)

    // pre-convert inputs to tf32-rounded fp32
    cvt_tf32_kernel<<<2048, 256>>>((const float4*)x,  (float4*)xtf,  in_sizes[0] / 4);
    cvt_tf32_kernel<<<2048, 256>>>((const float4*)w1, (float4*)w1tf, in_sizes[1] / 4);
    cvt_tf32_kernel<<<2048, 256>>>((const float4*)w2, (float4*)w2tf, in_sizes[2] / 4);

    cudaFuncSetAttribute(tc_gemm<true>,  cudaFuncAttributeMaxDynamicSharedMemorySize, SMEM_DYN);
    cudaFuncSetAttribute(tc_gemm<false>, cudaFuncAttributeMaxDynamicSharedMemorySize, SMEM_DYN);

    // GEMM1 + GELU: [T,H] @ [H,F] -> inter [T,F] per expert
    dim3 g1(T / BM, FDIM / BN, NEXP);
    tc_gemm<true><<<g1, 256, SMEM_DYN>>>(xtf, w1tf, inter, T, FDIM, HDIM);
    // GEMM2: inter [T,F] @ [F,H] -> out [T,H] per expert
    dim3 g2(T / BM, HDIM / BN, NEXP);
    tc_gemm<false><<<g2, 256, SMEM_DYN>>>(inter, w2tf, out, T, HDIM, FDIM);
}